// round 2
// baseline (speedup 1.0000x reference)
#include <cuda_runtime.h>

#define TPB 256
#define LDH 132            // padded row stride (floats) for 128-wide activation rows
#define K0  648

// ---------------------------------------------------------------------------
// One CTA = 64 positions (fixed (ahi,awi), 2 consecutive h rows, all 32 w).
// Grid = 49 * 16 = 784 CTAs, 2 CTAs/SM (16 warps/SM).
// Phase A: base[64,128] = q_feat @ W0[:648]  (implicit gather GEMM),
//          base kept in REGISTERS (4x8 per thread) across all branches.
// Branch i: h1 = relu(base + b0 + s*(32^(i+1)*P + Q)); h2=relu(h1@W1+b1);
//           h3 = relu(h2@W2+b2); y += 0.25*(h3@W3+b3).
// ---------------------------------------------------------------------------

__device__ __forceinline__ void gemm_layer64(
    const float* __restrict__ src,      // smem [64][LDH] row-major
    const float* __restrict__ Wg,       // global [128][128]
    const float* __restrict__ bias,     // smem [128]
    float* __restrict__ dst,            // smem [64][LDH]
    float* __restrict__ sB,             // smem staging [32][128]
    int tx, int ty, int tid)
{
    float acc[4][8];
#pragma unroll
    for (int i = 0; i < 4; i++)
#pragma unroll
        for (int j = 0; j < 8; j++) acc[i][j] = 0.f;

    for (int kc = 0; kc < 4; kc++) {
        // stage W chunk [32][128] = 1024 float4, 4 per thread
#pragma unroll
        for (int t = 0; t < 4; t++) {
            int f = tid + t * TPB;
            int k = f >> 5, j = (f & 31) * 4;
            *(float4*)&sB[k * 128 + j] = *(const float4*)&Wg[(kc * 32 + k) * 128 + j];
        }
        __syncthreads();
#pragma unroll 4
        for (int k4 = 0; k4 < 8; k4++) {
            float4 a4[4];
#pragma unroll
            for (int i = 0; i < 4; i++)
                a4[i] = *(const float4*)&src[(ty * 4 + i) * LDH + kc * 32 + k4 * 4];
#pragma unroll
            for (int kk = 0; kk < 4; kk++) {
                float4 bb0 = *(const float4*)&sB[(k4 * 4 + kk) * 128 + tx * 8];
                float4 bb1 = *(const float4*)&sB[(k4 * 4 + kk) * 128 + tx * 8 + 4];
                float bv[8] = {bb0.x, bb0.y, bb0.z, bb0.w, bb1.x, bb1.y, bb1.z, bb1.w};
                float av[4];
                av[0] = (kk == 0) ? a4[0].x : (kk == 1) ? a4[0].y : (kk == 2) ? a4[0].z : a4[0].w;
                av[1] = (kk == 0) ? a4[1].x : (kk == 1) ? a4[1].y : (kk == 2) ? a4[1].z : a4[1].w;
                av[2] = (kk == 0) ? a4[2].x : (kk == 1) ? a4[2].y : (kk == 2) ? a4[2].z : a4[2].w;
                av[3] = (kk == 0) ? a4[3].x : (kk == 1) ? a4[3].y : (kk == 2) ? a4[3].z : a4[3].w;
#pragma unroll
                for (int i = 0; i < 4; i++)
#pragma unroll
                    for (int j = 0; j < 8; j++) acc[i][j] = fmaf(av[i], bv[j], acc[i][j]);
            }
        }
        __syncthreads();
    }
    // epilogue: bias + relu, row-major float4 stores
#pragma unroll
    for (int i = 0; i < 4; i++) {
        int r = ty * 4 + i;
        float4 v0, v1;
        v0.x = fmaxf(acc[i][0] + bias[tx * 8 + 0], 0.f);
        v0.y = fmaxf(acc[i][1] + bias[tx * 8 + 1], 0.f);
        v0.z = fmaxf(acc[i][2] + bias[tx * 8 + 2], 0.f);
        v0.w = fmaxf(acc[i][3] + bias[tx * 8 + 3], 0.f);
        v1.x = fmaxf(acc[i][4] + bias[tx * 8 + 4], 0.f);
        v1.y = fmaxf(acc[i][5] + bias[tx * 8 + 5], 0.f);
        v1.z = fmaxf(acc[i][6] + bias[tx * 8 + 6], 0.f);
        v1.w = fmaxf(acc[i][7] + bias[tx * 8 + 7], 0.f);
        *(float4*)&dst[r * LDH + tx * 8]     = v0;
        *(float4*)&dst[r * LDH + tx * 8 + 4] = v1;
    }
}

__global__ __launch_bounds__(TPB, 2)
void inr_fused_kernel(const float* __restrict__ inp,
                      const float* __restrict__ W0, const float* __restrict__ b0,
                      const float* __restrict__ W1, const float* __restrict__ b1,
                      const float* __restrict__ W2, const float* __restrict__ b2,
                      const float* __restrict__ W3, const float* __restrict__ b3,
                      float* __restrict__ outp)
{
    extern __shared__ float sm[];
    float* sX   = sm;                        // 64*LDH
    float* sY   = sX + 64 * LDH;             // 64*LDH
    float* sStg = sY + 64 * LDH;             // 4608 floats: phaseA sA[24*64]+sB[24*128]; layers sB[32*128]
    float* sW3  = sStg + 4608;               // 128*12
    float* sb0  = sW3 + 128 * 12;            // 128
    float* sb1  = sb0 + 128;
    float* sb2  = sb1 + 128;
    float* sP   = sb2 + 128;                 // W0[716]+W0[717]
    float* sQ   = sP + 128;                  // W0[718]+W0[719]
    float* sb3  = sQ + 128;                  // 16
    int2*  sLut = (int2*)(sb3 + 16);         // 648 entries

    const int tid = threadIdx.x;
    const int tx = tid & 15, ty = tid >> 4;

    const int blk  = blockIdx.x;
    const int ablk = blk >> 4;               // 0..48 -> (ahi,awi)
    const int hgrp = blk & 15;               // 0..15 -> hi group of 2
    const int ahi  = ablk / 7;
    const int awi  = ablk % 7;
    const int inpBase = ahi * 7168 + awi * 1024 + hgrp * 64;

    // ---- init LUT + constants ----
    for (int k = tid; k < K0; k += TPB) {
        int aj = k % 3, ai = (k / 3) % 3, kj = (k / 9) % 3, ki = (k / 27) % 3, ch = k / 81;
        int off = ch * 50176 + (ai - 1) * 7168 + (aj - 1) * 1024 + (ki - 1) * 32 + (kj - 1);
        sLut[k] = make_int2(off, ai | (aj << 4) | (ki << 8) | (kj << 12));
    }
    for (int c = tid; c < 128; c += TPB) {
        sb0[c] = b0[c]; sb1[c] = b1[c]; sb2[c] = b2[c];
        sP[c] = W0[716 * 128 + c] + W0[717 * 128 + c];
        sQ[c] = W0[718 * 128 + c] + W0[719 * 128 + c];
    }
    for (int e = tid; e < 128 * 12; e += TPB) sW3[e] = W3[e];
    if (tid < 12) sb3[tid] = b3[tid];
    __syncthreads();

    // ---------------- Phase A: base = q_feat @ W0[:648] (chunks of 24) -------
    float* sA  = sStg;               // [24][64]
    float* sBw = sStg + 24 * 64;     // [24][128]

    float base_[4][8];
#pragma unroll
    for (int i = 0; i < 4; i++)
#pragma unroll
        for (int j = 0; j < 8; j++) base_[i][j] = 0.f;

    for (int kc = 0; kc < 27; kc++) {
        // gather A chunk [24][64] : 1536 elems, 6 per thread
#pragma unroll
        for (int t = 0; t < 6; t++) {
            int e = tid + t * TPB;
            int k = e >> 6, m = e & 63;
            int2 lu = sLut[kc * 24 + k];
            int ai = lu.y & 15, aj = (lu.y >> 4) & 15, ki = (lu.y >> 8) & 15, kj = (lu.y >> 12) & 15;
            int hi = hgrp * 2 + (m >> 5), wi = m & 31;
            bool ok = (unsigned)(ahi + ai - 1) < 7u && (unsigned)(awi + aj - 1) < 7u
                   && (unsigned)(hi + ki - 1) < 32u && (unsigned)(wi + kj - 1) < 32u;
            sA[k * 64 + m] = ok ? inp[inpBase + m + lu.x] : 0.f;
        }
        // stage W0 chunk [24][128] : 768 float4, 3 per thread
#pragma unroll
        for (int t = 0; t < 3; t++) {
            int f = tid + t * TPB;
            int k = f >> 5, j = (f & 31) * 4;
            *(float4*)&sBw[k * 128 + j] = *(const float4*)&W0[(kc * 24 + k) * 128 + j];
        }
        __syncthreads();
#pragma unroll 6
        for (int k = 0; k < 24; k++) {
            float4 a4 = *(const float4*)&sA[k * 64 + ty * 4];
            float4 bb0 = *(const float4*)&sBw[k * 128 + tx * 8];
            float4 bb1 = *(const float4*)&sBw[k * 128 + tx * 8 + 4];
            float av[4] = {a4.x, a4.y, a4.z, a4.w};
            float bv[8] = {bb0.x, bb0.y, bb0.z, bb0.w, bb1.x, bb1.y, bb1.z, bb1.w};
#pragma unroll
            for (int i = 0; i < 4; i++)
#pragma unroll
                for (int j = 0; j < 8; j++) base_[i][j] = fmaf(av[i], bv[j], base_[i][j]);
        }
        __syncthreads();
    }

    // ---------------- 4 branches ----------------
    float y3[3] = {0.f, 0.f, 0.f};
    float powv = 32.f;
    const int p0 = tid * 3;
    const int yr = p0 / 12;           // same row for all 3 outputs (12 | per-row outputs)
    for (int br = 0; br < 4; br++) {
        // h1 = relu(base + b0 + s*(powv*P + Q)) -> sX (from registers)
#pragma unroll
        for (int i = 0; i < 4; i++) {
            int r = ty * 4 + i;
            float s = 1.f;
            if (hgrp == 0 && r < 4) s = (r < 2) ? 0.0625f : (2.f / 7.f);
#pragma unroll
            for (int j = 0; j < 8; j++) {
                int c = tx * 8 + j;
                float u = base_[i][j] + sb0[c] + s * fmaf(powv, sP[c], sQ[c]);
                sX[r * LDH + c] = fmaxf(u, 0.f);
            }
        }
        __syncthreads();

        gemm_layer64(sX, W1, sb1, sY, sStg, tx, ty, tid);   // h2 -> sY
        __syncthreads();
        gemm_layer64(sY, W2, sb2, sX, sStg, tx, ty, tid);   // h3 -> sX
        __syncthreads();

        // y += 0.25 * (h3 @ W3 + b3) : 64*12 = 768 outputs, 3 per thread (same row)
        {
            float a0 = sb3[(p0 + 0) % 12];
            float a1 = sb3[(p0 + 1) % 12];
            float a2 = sb3[(p0 + 2) % 12];
            const float* hrow = &sX[yr * LDH];
#pragma unroll 8
            for (int k4 = 0; k4 < 32; k4++) {
                float4 hv = *(const float4*)&hrow[k4 * 4];
                const float* w = &sW3[(k4 * 4) * 12];
                a0 = fmaf(hv.x, w[(p0 + 0) % 12], a0);
                a1 = fmaf(hv.x, w[(p0 + 1) % 12], a1);
                a2 = fmaf(hv.x, w[(p0 + 2) % 12], a2);
                a0 = fmaf(hv.y, w[12 + (p0 + 0) % 12], a0);
                a1 = fmaf(hv.y, w[12 + (p0 + 1) % 12], a1);
                a2 = fmaf(hv.y, w[12 + (p0 + 2) % 12], a2);
                a0 = fmaf(hv.z, w[24 + (p0 + 0) % 12], a0);
                a1 = fmaf(hv.z, w[24 + (p0 + 1) % 12], a1);
                a2 = fmaf(hv.z, w[24 + (p0 + 2) % 12], a2);
                a0 = fmaf(hv.w, w[36 + (p0 + 0) % 12], a0);
                a1 = fmaf(hv.w, w[36 + (p0 + 1) % 12], a1);
                a2 = fmaf(hv.w, w[36 + (p0 + 2) % 12], a2);
            }
            y3[0] += 0.25f * a0;
            y3[1] += 0.25f * a1;
            y3[2] += 0.25f * a2;
        }
        __syncthreads();
        powv *= 32.f;
    }

    // ---------------- scatter with pixel shuffle ----------------
#pragma unroll
    for (int s3 = 0; s3 < 3; s3++) {
        int p = p0 + s3;
        int r = p / 12, c = p % 12;
        int hi = hgrp * 2 + (r >> 5), wi = r & 31;
        int rgb = c >> 2, pr = (c >> 1) & 1, qc = c & 1;
        outp[rgb * 200704 + ahi * 28672 + awi * 4096 + (2 * hi + pr) * 64 + (2 * wi + qc)] = y3[s3];
    }
}

extern "C" void kernel_launch(void* const* d_in, const int* in_sizes, int n_in,
                              void* d_out, int out_size)
{
    (void)in_sizes; (void)n_in; (void)out_size;
    const float* inp = (const float*)d_in[0];
    const float* W0  = (const float*)d_in[1];
    const float* b0  = (const float*)d_in[2];
    const float* W1  = (const float*)d_in[3];
    const float* b1  = (const float*)d_in[4];
    const float* W2  = (const float*)d_in[5];
    const float* b2  = (const float*)d_in[6];
    const float* W3  = (const float*)d_in[7];
    const float* b3  = (const float*)d_in[8];
    float* outp = (float*)d_out;

    size_t smem_floats = 2 * 64 * LDH + 4608 + 128 * 12 + 5 * 128 + 16 + 648 * 2;
    size_t smem = smem_floats * sizeof(float);

    cudaFuncSetAttribute(inr_fused_kernel,
                         cudaFuncAttributeMaxDynamicSharedMemorySize, (int)smem);

    inr_fused_kernel<<<784, TPB, smem>>>(inp, W0, b0, W1, b1, W2, b2, W3, b3, outp);
}

// round 4
// speedup vs baseline: 2.2385x; 2.2385x over previous
#include <cuda_runtime.h>
#include <cuda_bf16.h>
#include <stdint.h>

#define TPB 256

// ---------------- smem byte layout ----------------
// Branch phase:
#define OFF_A_HI   0         // h tile hi: [128 rows][256B] (32 KB)
#define OFF_A_LO   32768     // h tile lo  (32 KB)
#define OFF_W1HI   65536
#define OFF_W1LO   98304
#define OFF_W2HI   131072
#define OFF_W2LO   163840
#define OFF_W3HI   196608    // [16 rows][256B] = 4 KB
#define OFF_W3LO   200704
// Phase-A aliases:
#define PA_AHI     0         // A chunk hi: [128 rows][128B] (16 KB)
#define PA_ALO     16384
#define PA_W0(b)   (65536 + (b) * 32768)   // +0 hi, +16384 lo
#define PA_STG     131072                  // fp32 staging [64][129] = 33024 B
// Constants:
#define OFF_SB0    204800
#define OFF_SB1    205312
#define OFF_SB2    205824
#define OFF_SP     206336
#define OFF_SQ     206848
#define OFF_SB3    207360
#define OFF_LUT    207424    // 648 * 8
#define SMEM_BYTES 212608

// ---------------- device weight images ----------------
__device__ __align__(16) __nv_bfloat16 gW0_hi[11 * 8192];
__device__ __align__(16) __nv_bfloat16 gW0_lo[11 * 8192];
__device__ __align__(16) __nv_bfloat16 gW1_hi[16384];
__device__ __align__(16) __nv_bfloat16 gW1_lo[16384];
__device__ __align__(16) __nv_bfloat16 gW2_hi[16384];
__device__ __align__(16) __nv_bfloat16 gW2_lo[16384];
__device__ __align__(16) __nv_bfloat16 gW3_hi[2048];
__device__ __align__(16) __nv_bfloat16 gW3_lo[2048];

// ---------------- asm helpers ----------------
__device__ __forceinline__ uint32_t smem_u32(const void* p) {
    uint32_t a;
    asm("{ .reg .u64 t; cvta.to.shared.u64 t, %1; cvt.u32.u64 %0, t; }" : "=r"(a) : "l"(p));
    return a;
}
__device__ __forceinline__ void ldmx4(uint32_t r[4], uint32_t addr) {
    asm volatile("ldmatrix.sync.aligned.m8n8.x4.shared.b16 {%0,%1,%2,%3}, [%4];"
        : "=r"(r[0]), "=r"(r[1]), "=r"(r[2]), "=r"(r[3]) : "r"(addr));
}
__device__ __forceinline__ void ldmx2(uint32_t r[2], uint32_t addr) {
    asm volatile("ldmatrix.sync.aligned.m8n8.x2.shared.b16 {%0,%1}, [%2];"
        : "=r"(r[0]), "=r"(r[1]) : "r"(addr));
}
__device__ __forceinline__ void mma16816(float* d, const uint32_t a[4], const uint32_t b[2]) {
    asm volatile("mma.sync.aligned.m16n8k16.row.col.f32.bf16.bf16.f32 "
        "{%0,%1,%2,%3}, {%4,%5,%6,%7}, {%8,%9}, {%0,%1,%2,%3};"
        : "+f"(d[0]), "+f"(d[1]), "+f"(d[2]), "+f"(d[3])
        : "r"(a[0]), "r"(a[1]), "r"(a[2]), "r"(a[3]), "r"(b[0]), "r"(b[1]));
}
__device__ __forceinline__ void split_pack(float v0, float v1, uint32_t& hi, uint32_t& lo) {
    __nv_bfloat16 h0 = __float2bfloat16(v0), h1 = __float2bfloat16(v1);
    float l0 = v0 - __bfloat162float(h0), l1 = v1 - __bfloat162float(h1);
    __nv_bfloat162 hp; hp.x = h0; hp.y = h1;
    __nv_bfloat162 lp; lp.x = __float2bfloat16(l0); lp.y = __float2bfloat16(l1);
    hi = *(uint32_t*)&hp; lo = *(uint32_t*)&lp;
}

// 3-term split GEMM accumulate. A tiles [.. rows][2^RLOG bytes] swizzled, B same.
// Warp computes m-rows [mbase, mbase+64) x n-cols [nbase, nbase+8*NT).
template<int KS, int NT, int RLOG>
__device__ __forceinline__ void gemm3(uint32_t aHi, uint32_t aLo, uint32_t bHi, uint32_t bLo,
                                      int mbase, int nbase, float* acc, int lane)
{
    const int rA = mbase + (lane & 15);
    const int selA = lane >> 4;
    const int rB = nbase + (lane & 7);
    const int selB = (lane >> 3) & 1;
    const uint32_t aHiRow = aHi + (rA << RLOG);
    const uint32_t aLoRow = aLo + (rA << RLOG);
    const uint32_t bHiRow = bHi + (rB << RLOG);
    const uint32_t bLoRow = bLo + (rB << RLOG);
    const int xorA = rA & 7, xorB = rB & 7;
#pragma unroll 2
    for (int ks = 0; ks < KS; ks++) {
        const uint32_t offA = (uint32_t)((((ks * 2 + selA) ^ xorA) << 4));
        const uint32_t offB = (uint32_t)((((ks * 2 + selB) ^ xorB) << 4));
        uint32_t ah[4][4], al[4][4], bh[NT][2], bl[NT][2];
#pragma unroll
        for (int mt = 0; mt < 4; mt++) {
            ldmx4(ah[mt], aHiRow + (mt << (RLOG + 4)) + offA);
            ldmx4(al[mt], aLoRow + (mt << (RLOG + 4)) + offA);
        }
#pragma unroll
        for (int nt = 0; nt < NT; nt++) {
            ldmx2(bh[nt], bHiRow + (nt << (RLOG + 3)) + offB);
            ldmx2(bl[nt], bLoRow + (nt << (RLOG + 3)) + offB);
        }
#pragma unroll
        for (int mt = 0; mt < 4; mt++)
#pragma unroll
            for (int nt = 0; nt < NT; nt++) {
                float* d = acc + (mt * NT + nt) * 4;
                mma16816(d, ah[mt], bh[nt]);
                mma16816(d, ah[mt], bl[nt]);
                mma16816(d, al[mt], bh[nt]);
            }
    }
}

// epilogue: acc (D frags) + bias (+cell term) -> relu -> split bf16 -> swizzled h tiles
template<bool EXTRA>
__device__ __forceinline__ void epi(char* sm, const float* acc, const float* bias,
                                    float powv, const float* sP, const float* sQ,
                                    int mg, int ng, int lane, int hgrp)
{
    const int rq = lane >> 2, nq = (lane & 3) * 2;
#pragma unroll
    for (int mt = 0; mt < 4; mt++) {
#pragma unroll
        for (int nt = 0; nt < 4; nt++) {
            int n = ng * 32 + nt * 8 + nq;
            float bb0 = bias[n], bb1 = bias[n + 1];
            float e0 = 0.f, e1 = 0.f;
            if (EXTRA) { e0 = fmaf(powv, sP[n], sQ[n]); e1 = fmaf(powv, sP[n + 1], sQ[n + 1]); }
            const float* a = acc + (mt * 4 + nt) * 4;
#pragma unroll
            for (int half = 0; half < 2; half++) {
                int r = mg * 64 + mt * 16 + rq + half * 8;
                float v0 = a[half * 2 + 0] + bb0;
                float v1 = a[half * 2 + 1] + bb1;
                if (EXTRA) {
                    float s = 1.f;
                    if (hgrp == 0 && r < 4) s = (r < 2) ? 0.0625f : (2.f / 7.f);
                    v0 += s * e0; v1 += s * e1;
                }
                v0 = fmaxf(v0, 0.f); v1 = fmaxf(v1, 0.f);
                uint32_t hi, lo;
                split_pack(v0, v1, hi, lo);
                int off = (r << 8) + ((((n >> 3) ^ (r & 7)) << 4)) + (n & 7) * 2;
                *(uint32_t*)(sm + OFF_A_HI + off) = hi;
                *(uint32_t*)(sm + OFF_A_LO + off) = lo;
            }
        }
    }
}

// ---------------- prep kernel: transpose + split + swizzle weights ----------------
__global__ void prep_kernel(const float* __restrict__ W0, const float* __restrict__ W1,
                            const float* __restrict__ W2, const float* __restrict__ W3) {
    int idx = blockIdx.x * 256 + threadIdx.x;
    const int n0 = 11 * 8192, n1 = 16384, n2 = 16384, n3 = 2048;
    if (idx < n0) {
        int c = idx >> 13, r = idx & 8191, n = r >> 6, k = r & 63, kk = c * 64 + k;
        float v = (kk < 648) ? W0[kk * 128 + n] : 0.f;
        __nv_bfloat16 h = __float2bfloat16(v);
        int byte = n * 128 + (((k >> 3) ^ (n & 7)) << 4) + (k & 7) * 2;
        gW0_hi[c * 8192 + (byte >> 1)] = h;
        gW0_lo[c * 8192 + (byte >> 1)] = __float2bfloat16(v - __bfloat162float(h));
    } else if (idx < n0 + n1) {
        int r = idx - n0, n = r >> 7, k = r & 127;
        float v = W1[k * 128 + n];
        __nv_bfloat16 h = __float2bfloat16(v);
        int byte = n * 256 + (((k >> 3) ^ (n & 7)) << 4) + (k & 7) * 2;
        gW1_hi[byte >> 1] = h;
        gW1_lo[byte >> 1] = __float2bfloat16(v - __bfloat162float(h));
    } else if (idx < n0 + n1 + n2) {
        int r = idx - n0 - n1, n = r >> 7, k = r & 127;
        float v = W2[k * 128 + n];
        __nv_bfloat16 h = __float2bfloat16(v);
        int byte = n * 256 + (((k >> 3) ^ (n & 7)) << 4) + (k & 7) * 2;
        gW2_hi[byte >> 1] = h;
        gW2_lo[byte >> 1] = __float2bfloat16(v - __bfloat162float(h));
    } else if (idx < n0 + n1 + n2 + n3) {
        int r = idx - n0 - n1 - n2, n = r >> 7, k = r & 127;
        float v = (n < 12) ? W3[k * 12 + n] : 0.f;
        __nv_bfloat16 h = __float2bfloat16(v);
        int byte = n * 256 + (((k >> 3) ^ (n & 7)) << 4) + (k & 7) * 2;
        gW3_hi[byte >> 1] = h;
        gW3_lo[byte >> 1] = __float2bfloat16(v - __bfloat162float(h));
    }
}

// ---------------- main kernel ----------------
__global__ __launch_bounds__(TPB, 1)
void inr_hmma_kernel(const float* __restrict__ inp,
                     const float* __restrict__ W0,
                     const float* __restrict__ b0g, const float* __restrict__ b1g,
                     const float* __restrict__ b2g, const float* __restrict__ b3g,
                     float* __restrict__ outp) {
    extern __shared__ char sm[];
    const uint32_t sbase = smem_u32(sm);
    const int tid = threadIdx.x;
    const int lane = tid & 31, w = tid >> 5;
    const int mg = w >> 2, ng = w & 3;

    const int blk = blockIdx.x;
    const int ablk = blk >> 3, hgrp = blk & 7;
    const int ahi = ablk / 7, awi = ablk % 7;
    const int inpBase = ahi * 7168 + awi * 1024 + hgrp * 128;

    float* sb0 = (float*)(sm + OFF_SB0);
    float* sb1 = (float*)(sm + OFF_SB1);
    float* sb2 = (float*)(sm + OFF_SB2);
    float* sP  = (float*)(sm + OFF_SP);
    float* sQ  = (float*)(sm + OFF_SQ);
    float* sb3 = (float*)(sm + OFF_SB3);
    int2*  lut = (int2*)(sm + OFF_LUT);
    float* stg = (float*)(sm + PA_STG);

    for (int c = tid; c < 128; c += TPB) {
        sb0[c] = b0g[c]; sb1[c] = b1g[c]; sb2[c] = b2g[c];
        sP[c] = W0[716 * 128 + c] + W0[717 * 128 + c];
        sQ[c] = W0[718 * 128 + c] + W0[719 * 128 + c];
    }
    if (tid < 12) sb3[tid] = b3g[tid];
    for (int k = tid; k < 648; k += TPB) {
        int aj = k % 3, ai = (k / 3) % 3, kj = (k / 9) % 3, ki = (k / 27) % 3, ch = k / 81;
        int off = ch * 50176 + (ai - 1) * 7168 + (aj - 1) * 1024 + (ki - 1) * 32 + (kj - 1);
        lut[k] = make_int2(off, ai | (aj << 4) | (ki << 8) | (kj << 12));
    }
    __syncthreads();

    // ---- gather lambda-ish macro pieces ----
    auto gather = [&](int c) {
#pragma unroll 4
        for (int t = 0; t < 32; t++) {
            int e = tid + t * TPB;
            int k = e >> 7, m = e & 127;
            int kk = c * 64 + k;
            float v = 0.f;
            if (kk < 648) {
                int2 lu = lut[kk];
                int ai = lu.y & 15, aj = (lu.y >> 4) & 15, ki = (lu.y >> 8) & 15, kj = (lu.y >> 12) & 15;
                int hi = hgrp * 4 + (m >> 5), wi = m & 31;
                bool ok = (unsigned)(ahi + ai - 1) < 7u && (unsigned)(awi + aj - 1) < 7u
                       && (unsigned)(hi + ki - 1) < 32u && (unsigned)(wi + kj - 1) < 32u;
                v = ok ? inp[inpBase + m + lu.x] : 0.f;
            }
            stg[k * 129 + m] = v;
        }
    };
    auto copyW0 = [&](int c, int buf) {
        const uint4* sh = (const uint4*)(gW0_hi + c * 8192);
        const uint4* sl = (const uint4*)(gW0_lo + c * 8192);
        uint4* dh = (uint4*)(sm + PA_W0(buf));
        uint4* dl = (uint4*)(sm + PA_W0(buf) + 16384);
#pragma unroll
        for (int t = 0; t < 4; t++) { dh[tid + t * TPB] = sh[tid + t * TPB]; dl[tid + t * TPB] = sl[tid + t * TPB]; }
    };
    auto convert = [&]() {
        int m = tid & 127, kh = tid >> 7;
#pragma unroll
        for (int q = 0; q < 16; q++) {
            int kp = kh * 16 + q;
            float v0 = stg[(kp * 2) * 129 + m];
            float v1 = stg[(kp * 2 + 1) * 129 + m];
            uint32_t hi, lo;
            split_pack(v0, v1, hi, lo);
            int off = m * 128 + ((((kp >> 2) ^ (m & 7)) << 4)) + (kp & 3) * 4;
            *(uint32_t*)(sm + PA_AHI + off) = hi;
            *(uint32_t*)(sm + PA_ALO + off) = lo;
        }
    };

    // ================= Phase A: base = q_feat @ W0 =================
    float base_[64];
#pragma unroll
    for (int i = 0; i < 64; i++) base_[i] = 0.f;

    gather(0); copyW0(0, 0);
    __syncthreads();
    for (int c = 0; c < 11; c++) {
        convert();
        __syncthreads();
        gemm3<4, 4, 7>(sbase + PA_AHI, sbase + PA_ALO,
                       sbase + PA_W0(c & 1), sbase + PA_W0(c & 1) + 16384,
                       mg * 64, ng * 32, base_, lane);
        if (c < 10) { gather(c + 1); copyW0(c + 1, (c + 1) & 1); }
        __syncthreads();
    }

    // ---- load resident W1/W2/W3 ----
    {
        uint4* d;
        const uint4* s;
        d = (uint4*)(sm + OFF_W1HI); s = (const uint4*)gW1_hi;
#pragma unroll
        for (int t = 0; t < 8; t++) d[tid + t * TPB] = s[tid + t * TPB];
        d = (uint4*)(sm + OFF_W1LO); s = (const uint4*)gW1_lo;
#pragma unroll
        for (int t = 0; t < 8; t++) d[tid + t * TPB] = s[tid + t * TPB];
        d = (uint4*)(sm + OFF_W2HI); s = (const uint4*)gW2_hi;
#pragma unroll
        for (int t = 0; t < 8; t++) d[tid + t * TPB] = s[tid + t * TPB];
        d = (uint4*)(sm + OFF_W2LO); s = (const uint4*)gW2_lo;
#pragma unroll
        for (int t = 0; t < 8; t++) d[tid + t * TPB] = s[tid + t * TPB];
        ((uint4*)(sm + OFF_W3HI))[tid] = ((const uint4*)gW3_hi)[tid];
        ((uint4*)(sm + OFF_W3LO))[tid] = ((const uint4*)gW3_lo)[tid];
    }
    __syncthreads();

    // ================= 4 branches =================
    float yv[32];
#pragma unroll
    for (int i = 0; i < 32; i++) yv[i] = 0.f;
    float powv = 32.f;

    for (int br = 0; br < 4; br++) {
        // h1 = relu(base + b0 + s*(powv*P + Q))
        epi<true>(sm, base_, sb0, powv, sP, sQ, mg, ng, lane, hgrp);
        __syncthreads();

        float acc[64];
#pragma unroll
        for (int i = 0; i < 64; i++) acc[i] = 0.f;
        gemm3<8, 4, 8>(sbase + OFF_A_HI, sbase + OFF_A_LO,
                       sbase + OFF_W1HI, sbase + OFF_W1LO, mg * 64, ng * 32, acc, lane);
        __syncthreads();
        epi<false>(sm, acc, sb1, 0.f, sP, sQ, mg, ng, lane, hgrp);
        __syncthreads();

#pragma unroll
        for (int i = 0; i < 64; i++) acc[i] = 0.f;
        gemm3<8, 4, 8>(sbase + OFF_A_HI, sbase + OFF_A_LO,
                       sbase + OFF_W2HI, sbase + OFF_W2LO, mg * 64, ng * 32, acc, lane);
        __syncthreads();
        epi<false>(sm, acc, sb2, 0.f, sP, sQ, mg, ng, lane, hgrp);
        __syncthreads();

        if (ng == 0) {
            gemm3<8, 2, 8>(sbase + OFF_A_HI, sbase + OFF_A_LO,
                           sbase + OFF_W3HI, sbase + OFF_W3LO, mg * 64, 0, yv, lane);
        }
        __syncthreads();
        powv *= 32.f;
    }

    // ---- scatter (pixel shuffle); preds averaged: y = 0.25*sum + b3 ----
    if (ng == 0) {
        const int rq = lane >> 2, nq = (lane & 3) * 2;
#pragma unroll
        for (int mt = 0; mt < 4; mt++)
#pragma unroll
            for (int nt = 0; nt < 2; nt++)
#pragma unroll
                for (int half = 0; half < 2; half++)
#pragma unroll
                    for (int j = 0; j < 2; j++) {
                        int n = nt * 8 + nq + j;
                        if (n < 12) {
                            int p = mg * 64 + mt * 16 + rq + half * 8;
                            float val = 0.25f * yv[(mt * 2 + nt) * 4 + half * 2 + j] + sb3[n];
                            int hi = hgrp * 4 + (p >> 5), wi = p & 31;
                            int rgb = n >> 2, pr = (n >> 1) & 1, qc = n & 1;
                            outp[rgb * 200704 + ahi * 28672 + awi * 4096 +
                                 (2 * hi + pr) * 64 + (2 * wi + qc)] = val;
                        }
                    }
    }
}

extern "C" void kernel_launch(void* const* d_in, const int* in_sizes, int n_in,
                              void* d_out, int out_size) {
    (void)in_sizes; (void)n_in; (void)out_size;
    const float* inp = (const float*)d_in[0];
    const float* W0  = (const float*)d_in[1];
    const float* b0  = (const float*)d_in[2];
    const float* W1  = (const float*)d_in[3];
    const float* b1  = (const float*)d_in[4];
    const float* W2  = (const float*)d_in[5];
    const float* b2  = (const float*)d_in[6];
    const float* W3  = (const float*)d_in[7];
    const float* b3  = (const float*)d_in[8];
    float* outp = (float*)d_out;

    const int prep_tasks = 11 * 8192 + 16384 + 16384 + 2048;
    prep_kernel<<<(prep_tasks + 255) / 256, 256>>>(W0, W1, W2, W3);

    cudaFuncSetAttribute(inr_hmma_kernel, cudaFuncAttributeMaxDynamicSharedMemorySize, SMEM_BYTES);
    inr_hmma_kernel<<<392, TPB, SMEM_BYTES>>>(inp, W0, b0, b1, b2, b3, outp);
}

// round 5
// speedup vs baseline: 3.1554x; 1.4096x over previous
#include <cuda_runtime.h>
#include <cuda_bf16.h>
#include <stdint.h>

#define TPB 256

// ---------------- smem layout (bytes) ----------------
#define OFF_A_HI   0         // A tile hi: [64 rows][256B] (16 KB)
#define OFF_A_LO   16384     // A tile lo (16 KB)
#define OFF_SB0    32768
#define OFF_SB1    33280
#define OFF_SB2    33792
#define OFF_SP     34304
#define OFF_SQ     34816
#define OFF_SB3    35328     // 64 B
#define OFF_LUT    35392     // 648 * 8
#define SMEM_BYTES 40960

// ---------------- device weight images: mma.sync B-fragment packed ----------------
// entry (uint2) index = (kblk * nbStride + nblk) * 32 + lane
// lane = (n&7)*4 + ((k>>1)&3); reg = (k>>3)&1; half = k&1
__device__ __align__(16) __nv_bfloat16 gW0_hi[90112];  // 704 x 128
__device__ __align__(16) __nv_bfloat16 gW0_lo[90112];
__device__ __align__(16) __nv_bfloat16 gW1_hi[16384];  // 128 x 128
__device__ __align__(16) __nv_bfloat16 gW1_lo[16384];
__device__ __align__(16) __nv_bfloat16 gW2_hi[16384];
__device__ __align__(16) __nv_bfloat16 gW2_lo[16384];
__device__ __align__(16) __nv_bfloat16 gW3_hi[2048];   // 128 x 16 (12 padded)
__device__ __align__(16) __nv_bfloat16 gW3_lo[2048];

// ---------------- asm helpers ----------------
__device__ __forceinline__ uint32_t smem_u32(const void* p) {
    uint32_t a;
    asm("{ .reg .u64 t; cvta.to.shared.u64 t, %1; cvt.u32.u64 %0, t; }" : "=r"(a) : "l"(p));
    return a;
}
__device__ __forceinline__ void ldmx4(uint32_t r[4], uint32_t addr) {
    asm volatile("ldmatrix.sync.aligned.m8n8.x4.shared.b16 {%0,%1,%2,%3}, [%4];"
        : "=r"(r[0]), "=r"(r[1]), "=r"(r[2]), "=r"(r[3]) : "r"(addr));
}
__device__ __forceinline__ void mma16816(float* d, const uint32_t a[4], uint32_t b0, uint32_t b1) {
    asm volatile("mma.sync.aligned.m16n8k16.row.col.f32.bf16.bf16.f32 "
        "{%0,%1,%2,%3}, {%4,%5,%6,%7}, {%8,%9}, {%0,%1,%2,%3};"
        : "+f"(d[0]), "+f"(d[1]), "+f"(d[2]), "+f"(d[3])
        : "r"(a[0]), "r"(a[1]), "r"(a[2]), "r"(a[3]), "r"(b0), "r"(b1));
}
__device__ __forceinline__ void split_pack(float v0, float v1, uint32_t& hi, uint32_t& lo) {
    __nv_bfloat16 h0 = __float2bfloat16(v0), h1 = __float2bfloat16(v1);
    float l0 = v0 - __bfloat162float(h0), l1 = v1 - __bfloat162float(h1);
    __nv_bfloat162 hp; hp.x = h0; hp.y = h1;
    __nv_bfloat162 lp; lp.x = __float2bfloat16(l0); lp.y = __float2bfloat16(l1);
    hi = *(uint32_t*)&hp; lo = *(uint32_t*)&lp;
}

// 3-term split GEMM; A (hi/lo) from swizzled smem via ldmatrix, B frags direct from global.
// Warp computes rows [mrow, mrow+16) x cols [nblk0*8, (nblk0+NT)*8).
template<int KS, int NT, int RLOG>
__device__ __forceinline__ void gemm_gb(uint32_t aHi, uint32_t aLo,
    const uint2* __restrict__ gBh, const uint2* __restrict__ gBl,
    int kblk0, int nbStride, int nblk0, int mrow, float* acc, int lane)
{
    const int rA = mrow + (lane & 15);
    const int selA = lane >> 4;
    const uint32_t aHiRow = aHi + (rA << RLOG);
    const uint32_t aLoRow = aLo + (rA << RLOG);
    const int xorA = rA & 7;
#pragma unroll
    for (int ks = 0; ks < KS; ks++) {
        const uint32_t offA = ((uint32_t)(((ks * 2 + selA) ^ xorA))) << 4;
        uint32_t ah[4], al[4];
        ldmx4(ah, aHiRow + offA);
        ldmx4(al, aLoRow + offA);
        const uint2* bh = gBh + ((kblk0 + ks) * nbStride + nblk0) * 32 + lane;
        const uint2* bl = gBl + ((kblk0 + ks) * nbStride + nblk0) * 32 + lane;
#pragma unroll
        for (int nt = 0; nt < NT; nt++) {
            uint2 bhv = bh[nt * 32];
            uint2 blv = bl[nt * 32];
            float* d = acc + nt * 4;
            mma16816(d, ah, bhv.x, bhv.y);
            mma16816(d, ah, blv.x, blv.y);
            mma16816(d, al, bhv.x, bhv.y);
        }
    }
}

// epilogue: D frags (+bias [+cell term]) -> relu -> split bf16 -> swizzled smem A tile
template<bool EXTRA>
__device__ __forceinline__ void epi(char* sm, const float* acc, const float* bias,
                                    float powv, const float* sP, const float* sQ,
                                    int mg, int ng, int lane, int hgrp)
{
    const int rq = lane >> 2, nq = (lane & 3) * 2;
#pragma unroll
    for (int nt = 0; nt < 8; nt++) {
        int n = ng * 64 + nt * 8 + nq;
        float bb0 = bias[n], bb1 = bias[n + 1];
        float e0 = 0.f, e1 = 0.f;
        if (EXTRA) { e0 = fmaf(powv, sP[n], sQ[n]); e1 = fmaf(powv, sP[n + 1], sQ[n + 1]); }
        const float* a = acc + nt * 4;
#pragma unroll
        for (int half = 0; half < 2; half++) {
            int r = mg * 16 + rq + half * 8;
            float v0 = a[half * 2 + 0] + bb0;
            float v1 = a[half * 2 + 1] + bb1;
            if (EXTRA) {
                float s = 1.f;
                if (hgrp == 0 && r < 4) s = (r < 2) ? 0.0625f : (2.f / 7.f);
                v0 += s * e0; v1 += s * e1;
            }
            v0 = fmaxf(v0, 0.f); v1 = fmaxf(v1, 0.f);
            uint32_t hi, lo;
            split_pack(v0, v1, hi, lo);
            int off = (r << 8) + ((((n >> 3) ^ (r & 7)) << 4)) + (n & 7) * 2;
            *(uint32_t*)(sm + OFF_A_HI + off) = hi;
            *(uint32_t*)(sm + OFF_A_LO + off) = lo;
        }
    }
}

// ---------------- prep kernel: split + pack weights into B-fragment layout ----------------
__device__ __forceinline__ void pack_frag(__nv_bfloat16* dh, __nv_bfloat16* dl,
                                          float v, int k, int n, int nbStride) {
    __nv_bfloat16 h = __float2bfloat16(v);
    float lo = v - __bfloat162float(h);
    int entry = ((k >> 4) * nbStride + (n >> 3)) * 32 + (n & 7) * 4 + ((k >> 1) & 3);
    int idx16 = entry * 4 + ((k >> 3) & 1) * 2 + (k & 1);
    dh[idx16] = h;
    dl[idx16] = __float2bfloat16(lo);
}

__global__ void prep_kernel(const float* __restrict__ W0, const float* __restrict__ W1,
                            const float* __restrict__ W2, const float* __restrict__ W3) {
    int idx = blockIdx.x * 256 + threadIdx.x;
    const int n0 = 90112, n1 = 16384, n2 = 16384, n3 = 2048;
    if (idx < n0) {
        int k = idx >> 7, n = idx & 127;
        float v = (k < 648) ? W0[k * 128 + n] : 0.f;
        pack_frag(gW0_hi, gW0_lo, v, k, n, 16);
    } else if (idx < n0 + n1) {
        int r = idx - n0, k = r >> 7, n = r & 127;
        pack_frag(gW1_hi, gW1_lo, W1[k * 128 + n], k, n, 16);
    } else if (idx < n0 + n1 + n2) {
        int r = idx - n0 - n1, k = r >> 7, n = r & 127;
        pack_frag(gW2_hi, gW2_lo, W2[k * 128 + n], k, n, 16);
    } else if (idx < n0 + n1 + n2 + n3) {
        int r = idx - n0 - n1 - n2, k = r >> 4, n = r & 15;
        float v = (n < 12) ? W3[k * 12 + n] : 0.f;
        pack_frag(gW3_hi, gW3_lo, v, k, n, 2);
    }
}

// ---------------- main kernel ----------------
__global__ __launch_bounds__(TPB, 2)
void inr_hmma_kernel(const float* __restrict__ inp,
                     const float* __restrict__ W0,
                     const float* __restrict__ b0g, const float* __restrict__ b1g,
                     const float* __restrict__ b2g, const float* __restrict__ b3g,
                     float* __restrict__ outp) {
    extern __shared__ char sm[];
    const uint32_t sbase = smem_u32(sm);
    const int tid = threadIdx.x;
    const int lane = tid & 31, w = tid >> 5;
    const int mg = w >> 1, ng = w & 1;      // 4 m-groups x 2 n-groups

    const int blk = blockIdx.x;
    const int ablk = blk >> 4, hgrp = blk & 15;   // 64 rows = 2 h-rows
    const int ahi = ablk / 7, awi = ablk % 7;
    const int inpBase = ahi * 7168 + awi * 1024 + hgrp * 64;

    float* sb0 = (float*)(sm + OFF_SB0);
    float* sb1 = (float*)(sm + OFF_SB1);
    float* sb2 = (float*)(sm + OFF_SB2);
    float* sP  = (float*)(sm + OFF_SP);
    float* sQ  = (float*)(sm + OFF_SQ);
    float* sb3 = (float*)(sm + OFF_SB3);
    int2*  lut = (int2*)(sm + OFF_LUT);

    for (int c = tid; c < 128; c += TPB) {
        sb0[c] = b0g[c]; sb1[c] = b1g[c]; sb2[c] = b2g[c];
        sP[c] = W0[716 * 128 + c] + W0[717 * 128 + c];
        sQ[c] = W0[718 * 128 + c] + W0[719 * 128 + c];
    }
    if (tid < 12) sb3[tid] = b3g[tid];
    for (int k = tid; k < 648; k += TPB) {
        int aj = k % 3, ai = (k / 3) % 3, kj = (k / 9) % 3, ki = (k / 27) % 3, ch = k / 81;
        int off = ch * 50176 + (ai - 1) * 7168 + (aj - 1) * 1024 + (ki - 1) * 32 + (kj - 1);
        lut[k] = make_int2(off, ai | (aj << 4) | (ki << 8) | (kj << 12));
    }
    __syncthreads();

    const uint2* gw0h = (const uint2*)gW0_hi; const uint2* gw0l = (const uint2*)gW0_lo;
    const uint2* gw1h = (const uint2*)gW1_hi; const uint2* gw1l = (const uint2*)gW1_lo;
    const uint2* gw2h = (const uint2*)gW2_hi; const uint2* gw2l = (const uint2*)gW2_lo;
    const uint2* gw3h = (const uint2*)gW3_hi; const uint2* gw3l = (const uint2*)gW3_lo;

    // ================= Phase A: base = q_feat @ W0 (11 chunks of K=64) =================
    float base_[32];
#pragma unroll
    for (int i = 0; i < 32; i++) base_[i] = 0.f;

    const int gm = tid & 63;          // row (position)
    const int gstrip = tid >> 6;      // k-pair strip
    const int ghi = hgrp * 2 + (gm >> 5), gwi = gm & 31;

    for (int c = 0; c < 11; c++) {
        // fused gather + split + swizzled store: [64 rows][64 k]
#pragma unroll
        for (int q = 0; q < 8; q++) {
            int kp = gstrip * 8 + q;
            int kk = c * 64 + kp * 2;
            float v0 = 0.f, v1 = 0.f;
            if (kk < 648) {
                int2 lu = lut[kk];
                int ai = lu.y & 15, aj = (lu.y >> 4) & 15, ki = (lu.y >> 8) & 15, kj = (lu.y >> 12) & 15;
                bool ok = (unsigned)(ahi + ai - 1) < 7u && (unsigned)(awi + aj - 1) < 7u
                       && (unsigned)(ghi + ki - 1) < 32u && (unsigned)(gwi + kj - 1) < 32u;
                v0 = ok ? inp[inpBase + gm + lu.x] : 0.f;
            }
            if (kk + 1 < 648) {
                int2 lu = lut[kk + 1];
                int ai = lu.y & 15, aj = (lu.y >> 4) & 15, ki = (lu.y >> 8) & 15, kj = (lu.y >> 12) & 15;
                bool ok = (unsigned)(ahi + ai - 1) < 7u && (unsigned)(awi + aj - 1) < 7u
                       && (unsigned)(ghi + ki - 1) < 32u && (unsigned)(gwi + kj - 1) < 32u;
                v1 = ok ? inp[inpBase + gm + lu.x] : 0.f;
            }
            uint32_t hi, lo;
            split_pack(v0, v1, hi, lo);
            int off = gm * 128 + ((((kp >> 2) ^ (gm & 7)) << 4)) + (kp & 3) * 4;
            *(uint32_t*)(sm + OFF_A_HI + off) = hi;
            *(uint32_t*)(sm + OFF_A_LO + off) = lo;
        }
        __syncthreads();
        gemm_gb<4, 8, 7>(sbase + OFF_A_HI, sbase + OFF_A_LO, gw0h, gw0l,
                         c * 4, 16, ng * 8, mg * 16, base_, lane);
        __syncthreads();
    }

    // ================= 4 branches =================
    float y[4] = {0.f, 0.f, 0.f, 0.f};
    float powv = 32.f;

    for (int br = 0; br < 4; br++) {
        // h1 = relu(base + b0 + s*(powv*P + Q))
        epi<true>(sm, base_, sb0, powv, sP, sQ, mg, ng, lane, hgrp);
        __syncthreads();

        float acc[32];
#pragma unroll
        for (int i = 0; i < 32; i++) acc[i] = 0.f;
        gemm_gb<8, 8, 8>(sbase + OFF_A_HI, sbase + OFF_A_LO, gw1h, gw1l,
                         0, 16, ng * 8, mg * 16, acc, lane);
        __syncthreads();
        epi<false>(sm, acc, sb1, 0.f, sP, sQ, mg, ng, lane, hgrp);
        __syncthreads();

#pragma unroll
        for (int i = 0; i < 32; i++) acc[i] = 0.f;
        gemm_gb<8, 8, 8>(sbase + OFF_A_HI, sbase + OFF_A_LO, gw2h, gw2l,
                         0, 16, ng * 8, mg * 16, acc, lane);
        __syncthreads();
        epi<false>(sm, acc, sb2, 0.f, sP, sQ, mg, ng, lane, hgrp);
        __syncthreads();

        // y += h3 @ W3 (all 8 warps; ng selects 8-col block of N=16)
        gemm_gb<8, 1, 8>(sbase + OFF_A_HI, sbase + OFF_A_LO, gw3h, gw3l,
                         0, 2, ng, mg * 16, y, lane);
        __syncthreads();
        powv *= 32.f;
    }

    // ---- scatter (pixel shuffle); y = 0.25*sum + b3 ----
    {
        const int rq = lane >> 2, nq = (lane & 3) * 2;
#pragma unroll
        for (int half = 0; half < 2; half++)
#pragma unroll
            for (int j = 0; j < 2; j++) {
                int n = ng * 8 + nq + j;
                if (n < 12) {
                    int r = mg * 16 + rq + half * 8;
                    float val = 0.25f * y[half * 2 + j] + sb3[n];
                    int hi = hgrp * 2 + (r >> 5), wi = r & 31;
                    int rgb = n >> 2, pr = (n >> 1) & 1, qc = n & 1;
                    outp[rgb * 200704 + ahi * 28672 + awi * 4096 +
                         (2 * hi + pr) * 64 + (2 * wi + qc)] = val;
                }
            }
    }
}

extern "C" void kernel_launch(void* const* d_in, const int* in_sizes, int n_in,
                              void* d_out, int out_size) {
    (void)in_sizes; (void)n_in; (void)out_size;
    const float* inp = (const float*)d_in[0];
    const float* W0  = (const float*)d_in[1];
    const float* b0  = (const float*)d_in[2];
    const float* W1  = (const float*)d_in[3];
    const float* b1  = (const float*)d_in[4];
    const float* W2  = (const float*)d_in[5];
    const float* b2  = (const float*)d_in[6];
    const float* W3  = (const float*)d_in[7];
    const float* b3  = (const float*)d_in[8];
    float* outp = (float*)d_out;

    const int prep_tasks = 90112 + 16384 + 16384 + 2048;
    prep_kernel<<<(prep_tasks + 255) / 256, 256>>>(W0, W1, W2, W3);

    cudaFuncSetAttribute(inr_hmma_kernel, cudaFuncAttributeMaxDynamicSharedMemorySize, SMEM_BYTES);
    inr_hmma_kernel<<<784, TPB, SMEM_BYTES>>>(inp, W0, b0, b1, b2, b3, outp);
}